// round 2
// baseline (speedup 1.0000x reference)
#include <cuda_runtime.h>

#define KK      32
#define HH      4096
#define OUTN    4065
#define EPSV    1e-8f

#define WC       1024
#define NSTRIP   4
#define THREADS  512            // 16 warps; thread owns cols 2t, 2t+1
#define ROWTILES 37
#define ROUT     110
#define WIN      1055           // WC + KK - 1

// smem floats: img 1024 | P 1060 | wTot 20 | hist 32*512 float2 = 32768
#define SMEM_FLOATS (1024 + 1060 + 20 + 32 * THREADS * 2)

__device__ __forceinline__ void pf_row(float2& s, float2& v, float& ts, float& tv,
                                       const float* __restrict__ som,
                                       const float* __restrict__ var,
                                       int gr, int c0, int t,
                                       bool tailT, bool tailValid)
{
    const size_t ro = (size_t)gr * HH + c0 + 2 * t;
    s = *(const float2*)(som + ro);
    v = *(const float2*)(var + ro);
    if (tailT) {
        if (tailValid) {
            const size_t to = (size_t)gr * HH + c0 + 1024 + (t & 31);
            ts = som[to];
            tv = var[to];
        } else { ts = 0.f; tv = 1.f; }
    }
}

__global__ __launch_bounds__(THREADS, 1)
void som_boxdist_kernel(const float* __restrict__ img,
                        const float* __restrict__ som,
                        const float* __restrict__ var,
                        float* __restrict__ out)
{
    extern __shared__ __align__(16) float smem[];
    float*  s_img = smem;                   // 1024
    float*  P     = smem + 1024;            // exclusive prefix, idx 0..1055 (+pad)
    float*  wTot  = P + 1060;               // 16 warp totals (+pad)
    float2* hist  = (float2*)(wTot + 20);   // [32][512] float2

    const int t    = threadIdx.x;
    const int lane = t & 31;
    const int wid  = t >> 5;
    const int c0   = blockIdx.x * WC;
    const int r0   = blockIdx.y * ROUT;
    const int rows_out = min(ROUT, OUTN - r0);
    const int cols_out = min(WC,   OUTN - c0);
    const int rows_in  = rows_out + KK - 1;
    const bool tailValid = (HH - c0) > 1024;       // strip 3 has no tail cols
    const bool tailT     = (wid == 15) && (lane < 31);  // owns input col 1024+lane

    for (int i = t; i < KK * KK; i += THREADS) s_img[i] = img[i];

    // depth-2 register prefetch
    float2 sA, vA, sB, vB;
    float tsA = 0.f, tvA = 1.f, tsB = 0.f, tvB = 1.f;
    pf_row(sA, vA, tsA, tvA, som, var, r0, c0, t, tailT, tailValid);
    pf_row(sB, vB, tsB, tvB, som, var, min(r0 + 1, HH - 1), c0, t, tailT, tailValid);

    float acc0 = 0.f, acc1 = 0.f;           // vertical running sums
    const int imcol = (2 * t) & 31;         // image col phase for this thread

    __syncthreads();                        // s_img ready

    for (int ir = 0; ir < rows_in; ++ir) {
        const int gr = r0 + ir;

        // consume prefetched row, issue next
        float2 s, v; float ts, tv;
        if (ir & 1) {
            s = sB; v = vB; ts = tsB; tv = tvB;
            pf_row(sB, vB, tsB, tvB, som, var, min(gr + 2, HH - 1), c0, t, tailT, tailValid);
        } else {
            s = sA; v = vA; ts = tsA; tv = tvA;
            pf_row(sA, vA, tsA, tvA, som, var, min(gr + 2, HH - 1), c0, t, tailT, tailValid);
        }

        // per-pixel variance-weighted squared distance
        const int ph = (gr & 31) << 5;
        float2 iv = *(const float2*)&s_img[ph + imcol];
        float d0 = iv.x - s.x;
        float d1 = iv.y - s.y;
        float e0 = __fdividef(d0 * d0, v.x + EPSV);
        float e1 = __fdividef(d1 * d1, v.y + EPSV);

        // tail distance (cols 1024..1054), warp 15 lanes 0..30
        float td = 0.f;
        if (tailT && tailValid) {
            float tk = s_img[ph + lane];    // (1024+lane)&31 == lane
            float dd = tk - ts;
            td = __fdividef(dd * dd, tv + EPSV);
        }

        // warp inclusive scan of pair sums
        float sc = e0 + e1;
        #pragma unroll
        for (int o = 1; o < 32; o <<= 1) {
            float n = __shfl_up_sync(0xffffffffu, sc, o);
            if (lane >= o) sc += n;
        }
        // tail mini-scan inside warp 15
        float tsc = td;
        if (wid == 15) {
            #pragma unroll
            for (int o = 1; o < 32; o <<= 1) {
                float n = __shfl_up_sync(0xffffffffu, tsc, o);
                if (lane >= o) tsc += n;
            }
        }

        if (lane == 31) wTot[wid] = sc;
        __syncthreads();                    // (1) warp totals visible

        // carry = sum of totals of preceding warps (broadcast reads)
        float W = 0.f;
        for (int w = 0; w < wid; ++w) W += wTot[w];

        // write exclusive prefix P[0..1055]
        if (t == 0) P[0] = 0.f;
        P[2 * t + 1] = W + (sc - e1);
        P[2 * t + 2] = W + sc;
        if (wid == 15) {
            float tot15 = __shfl_sync(0xffffffffu, sc, 31);
            float P1024 = W + tot15;
            if (lane < 31) P[1025 + lane] = P1024 + tsc;
        }
        __syncthreads();                    // (2) P ready

        // horizontal box sums via prefix differences
        float2 pa = *(const float2*)&P[2 * t];
        float2 pb = *(const float2*)&P[2 * t + 32];
        float h0 = pb.x - pa.x;
        float h1 = pb.y - pa.y;

        // vertical sliding via 32-row history ring
        const int slot = ir & (KK - 1);
        float2 old = hist[slot * THREADS + t];
        if (ir < KK) { old.x = 0.f; old.y = 0.f; }
        acc0 += h0 - old.x;
        acc1 += h1 - old.y;
        hist[slot * THREADS + t] = make_float2(h0, h1);

        if (ir >= KK - 1) {
            const int orow = r0 + ir - (KK - 1);
            float* op = out + (size_t)orow * OUTN + c0 + 2 * t;
            if (2 * t     < cols_out) op[0] = acc0;
            if (2 * t + 1 < cols_out) op[1] = acc1;
        }
    }
}

extern "C" void kernel_launch(void* const* d_in, const int* in_sizes, int n_in,
                              void* d_out, int out_size)
{
    (void)in_sizes; (void)n_in; (void)out_size;
    const float* img = (const float*)d_in[0];
    const float* som = (const float*)d_in[1];
    const float* var = (const float*)d_in[2];
    float* out = (float*)d_out;

    const size_t shmem = (size_t)SMEM_FLOATS * sizeof(float);   // ~139.5 KB
    cudaFuncSetAttribute(som_boxdist_kernel,
                         cudaFuncAttributeMaxDynamicSharedMemorySize, (int)shmem);

    dim3 grid(NSTRIP, ROWTILES);
    som_boxdist_kernel<<<grid, THREADS, shmem>>>(img, som, var, out);
}

// round 4
// speedup vs baseline: 1.8062x; 1.8062x over previous
#include <cuda_runtime.h>

#define KK      32
#define HH      4096
#define OUTN    4065
#define EPSV    1e-8f

#define THREADS 512
#define NWARP   16
#define WPC     64           // output cols per warp
#define WC      1024         // output cols per block
#define NSTRIP  4
#define ROWTILES 37
#define ROUT    110
#define DEPTH   3            // prefetch depth (rows)

// smem floats: img 1024 + hist 16 warps * 32 slots * 64 cols = 32768
#define SMEM_FLOATS (1024 + NWARP * KK * WPC)

template<int B>
__device__ __forceinline__ void row_step(
    int ir, int r0, int lane,
    int col0, int col1, int col2, int base,
    const float* __restrict__ som, const float* __restrict__ var,
    const float* __restrict__ s_img, float* __restrict__ hp,
    float* __restrict__ out,
    float (&sb)[DEPTH][3], float (&vb)[DEPTH][3],
    float& acc0, float& acc1)
{
    const unsigned FULL = 0xffffffffu;
    const int gr = r0 + ir;

    // variance-weighted squared distances for the 3 input cols this lane owns
    const float iv = s_img[((gr & 31) << 5) + lane];
    const float d0 = iv - sb[B][0];
    const float d1 = iv - sb[B][1];
    const float d2 = iv - sb[B][2];
    const float e0 = __fdividef(d0 * d0, vb[B][0] + EPSV);
    const float e1 = __fdividef(d1 * d1, vb[B][1] + EPSV);
    const float e2 = __fdividef(d2 * d2, vb[B][2] + EPSV);

    // refill buffer B with row gr+DEPTH ASAP (clamped row => always valid)
    {
        const int pr = min(gr + DEPTH, HH - 1);
        const float* sr = som + (size_t)pr * HH;
        const float* vr = var + (size_t)pr * HH;
        sb[B][0] = __ldg(sr + col0); sb[B][1] = __ldg(sr + col1); sb[B][2] = __ldg(sr + col2);
        vb[B][0] = __ldg(vr + col0); vb[B][1] = __ldg(vr + col1); vb[B][2] = __ldg(vr + col2);
    }

    // three interleaved warp inclusive scans
    float S0 = e0, S1 = e1, S2 = e2;
#pragma unroll
    for (int o = 1; o < 32; o <<= 1) {
        float a0 = __shfl_up_sync(FULL, S0, o);
        float a1 = __shfl_up_sync(FULL, S1, o);
        float a2 = __shfl_up_sync(FULL, S2, o);
        if (lane >= o) { S0 += a0; S1 += a1; S2 += a2; }
    }
    // carry segment totals: S_j becomes inclusive prefix at input col 32j+lane
    const float T0 = __shfl_sync(FULL, S0, 31);
    const float T1 = __shfl_sync(FULL, S1, 31);
    S1 += T0;
    S2 += T0 + T1;
    const float D1 = S1 - S0;
    const float D2 = S2 - S1;

    // horizontal 32-wide window sums via prefix differences
    const float u1 = __shfl_up_sync(FULL, D1, 1);
    const float u2 = __shfl_up_sync(FULL, D2, 1);
    const float b0 = __shfl_sync(FULL, S0, 31);   // window @ warp col 0
    const float b1 = __shfl_sync(FULL, D1, 31);   // window @ warp col 32
    const float h0 = (lane == 0) ? b0 : u1;
    const float h1 = (lane == 0) ? b1 : u2;

    // vertical sliding window via warp-private 32-row smem ring (no sync needed)
    float* hs = hp + ((ir & 31) << 6);
    float o0 = 0.f, o1 = 0.f;
    if (ir >= KK) { o0 = hs[0]; o1 = hs[32]; }
    acc0 += h0 - o0;
    acc1 += h1 - o1;
    hs[0] = h0;
    hs[32] = h1;

    // emit output row once the 32-row window is full
    if (ir >= KK - 1) {
        const int orow = gr - (KK - 1);
        if (orow >= 0 && orow < OUTN) {
            float* op = out + (size_t)orow * OUTN + base;
            if (base < OUTN)      op[0]  = acc0;   // base <= 4063 always
            if (base + 32 < OUTN) op[32] = acc1;
        }
    }
}

__global__ __launch_bounds__(THREADS, 1)
void som_boxdist_kernel(const float* __restrict__ img,
                        const float* __restrict__ som,
                        const float* __restrict__ var,
                        float* __restrict__ out)
{
    extern __shared__ __align__(16) float smem[];
    float* s_img = smem;                 // 1024 floats
    float* hist  = smem + 1024;          // [warp][slot][2][32]

    const int t    = threadIdx.x;
    const int lane = t & 31;
    const int w    = t >> 5;
    const int c0   = blockIdx.x * WC;
    const int r0   = blockIdx.y * ROUT;
    const int rows_out = min(ROUT, OUTN - r0);
    const int rows_in  = rows_out + KK - 1;

    const int base = c0 + w * WPC + lane;        // lane's first input/output col
    const int col0 = min(base,      HH - 1);     // clamped (strip 3 right edge)
    const int col1 = min(base + 32, HH - 1);
    const int col2 = min(base + 64, HH - 1);

    for (int i = t; i < KK * KK; i += THREADS) s_img[i] = img[i];

    // depth-3 register prefetch ring
    float sb[DEPTH][3], vb[DEPTH][3];
#pragma unroll
    for (int d = 0; d < DEPTH; ++d) {
        const int pr = min(r0 + d, HH - 1);
        const float* sr = som + (size_t)pr * HH;
        const float* vr = var + (size_t)pr * HH;
        sb[d][0] = __ldg(sr + col0); sb[d][1] = __ldg(sr + col1); sb[d][2] = __ldg(sr + col2);
        vb[d][0] = __ldg(vr + col0); vb[d][1] = __ldg(vr + col1); vb[d][2] = __ldg(vr + col2);
    }

    __syncthreads();    // s_img ready (the ONLY barrier)

    float acc0 = 0.f, acc1 = 0.f;
    float* hp = hist + w * (KK * WPC) + lane;    // + slot*64 (+32 for 2nd col)

    const int nloop = ((rows_in + DEPTH - 1) / DEPTH) * DEPTH;

    for (int ir = 0; ir < nloop; ir += DEPTH) {
        row_step<0>(ir + 0, r0, lane, col0, col1, col2, base,
                    som, var, s_img, hp, out, sb, vb, acc0, acc1);
        row_step<1>(ir + 1, r0, lane, col0, col1, col2, base,
                    som, var, s_img, hp, out, sb, vb, acc0, acc1);
        row_step<2>(ir + 2, r0, lane, col0, col1, col2, base,
                    som, var, s_img, hp, out, sb, vb, acc0, acc1);
    }
}

extern "C" void kernel_launch(void* const* d_in, const int* in_sizes, int n_in,
                              void* d_out, int out_size)
{
    (void)in_sizes; (void)n_in; (void)out_size;
    const float* img = (const float*)d_in[0];
    const float* som = (const float*)d_in[1];
    const float* var = (const float*)d_in[2];
    float* out = (float*)d_out;

    const size_t shmem = (size_t)SMEM_FLOATS * sizeof(float);   // 135,168 B
    cudaFuncSetAttribute(som_boxdist_kernel,
                         cudaFuncAttributeMaxDynamicSharedMemorySize, (int)shmem);

    dim3 grid(NSTRIP, ROWTILES);
    som_boxdist_kernel<<<grid, THREADS, shmem>>>(img, som, var, out);
}